// round 16
// baseline (speedup 1.0000x reference)
#include <cuda_runtime.h>
#include <cuda_bf16.h>
#include <cstdint>

#define NN 50000
#define MM 24
#define AA 64
#define BB 32
#define KK 160   // 2A + B
#define OO 128   // 2A
#define EPSV 1e-5f
#define TPAD 168          // padded row stride (elements) for smem bf16 tiles
#define TILE_M 32
#define NT2 1563          // ceil(50000/32)
#define NCTA2 296         // 2 CTAs per SM
#define NTHR 384
#define EBLK 592          // elementwise kernels: 4 blocks/SM
#define TOT4 (NN * (AA / 4))      // 800000 float4 elements

// ---------------- scratch (static __device__, zero-init at load) ----------------
__device__ float g_t[(size_t)NN * KK];      // 32 MB
__device__ float g_y[(size_t)NN * OO];      // 25.6 MB
__device__ float g_core[(size_t)NN * AA];   // 12.8 MB
__device__ float g_stats1[2 * OO];          // re-zeroed by k_feat block 0 (ALL 256 entries)
__device__ float g_stats2[2 * AA];          // re-zeroed by k_feat block 0

// ---------------- helpers ----------------
__device__ __forceinline__ float softplus_fast(float x) {
    return fmaxf(x, 0.0f) + __logf(1.0f + __expf(-fabsf(x)));
}
__device__ __forceinline__ uint32_t smem_u32(const void* p) {
    return (uint32_t)__cvta_generic_to_shared(p);
}
__device__ __forceinline__ void ldsm_x4(uint32_t* r, uint32_t addr) {
    asm volatile("ldmatrix.sync.aligned.m8n8.x4.shared.b16 {%0,%1,%2,%3}, [%4];"
                 : "=r"(r[0]), "=r"(r[1]), "=r"(r[2]), "=r"(r[3]) : "r"(addr));
}
__device__ __forceinline__ void mma16816(float* d, const uint32_t* a,
                                         const uint32_t b0, const uint32_t b1) {
    asm volatile(
        "mma.sync.aligned.m16n8k16.row.col.f32.bf16.bf16.f32 "
        "{%0,%1,%2,%3}, {%4,%5,%6,%7}, {%8,%9}, {%0,%1,%2,%3};"
        : "+f"(d[0]), "+f"(d[1]), "+f"(d[2]), "+f"(d[3])
        : "r"(a[0]), "r"(a[1]), "r"(a[2]), "r"(a[3]), "r"(b0), "r"(b1));
}
__device__ __forceinline__ __nv_bfloat162 split_hi2(float x, float y,
                                                    float& rx, float& ry) {
    __nv_bfloat16 hx = __float2bfloat16(x);
    __nv_bfloat16 hy = __float2bfloat16(y);
    rx = x - __bfloat162float(hx);
    ry = y - __bfloat162float(hy);
    return __halves2bfloat162(hx, hy);
}

// ---------------- kernel 1: gather/reduce -> t[n][160] (proven, frozen) ----------------
__global__ void __launch_bounds__(128)
k_feat(const float* __restrict__ atom,
       const float* __restrict__ nbrfea,
       const int* __restrict__ nbridx,
       const float* __restrict__ bwi,
       const float* __restrict__ bwj) {
    if (blockIdx.x == 0) {
        for (int t = threadIdx.x; t < 2 * OO; t += 128) g_stats1[t] = 0.0f;
        if (threadIdx.x < 2 * AA) g_stats2[threadIdx.x] = 0.0f;
    }

    const int lane = threadIdx.x & 31;
    const int warp = threadIdx.x >> 5;
    const int n = blockIdx.x * 4 + warp;   // 12500*4 = 50000 exact

    float wm = 0.0f;
    int jv = 0;
    if (lane < MM) {
        wm = bwi[(size_t)n * MM + lane] * bwj[(size_t)n * MM + lane];
        jv = nbridx[(size_t)n * MM + lane];
    }
    float s = wm;
    #pragma unroll
    for (int o = 16; o; o >>= 1) s += __shfl_xor_sync(0xffffffffu, s, o);

    float a0 = 0.f, a1 = 0.f, bacc = 0.f;
    const float* nrow = nbrfea + (size_t)n * MM * BB;

    #pragma unroll
    for (int c = 0; c < 2; c++) {
        float2 ga[12];
        float  nb[12];
        float  wv[12];
        #pragma unroll
        for (int u = 0; u < 12; u++) {
            const int m = c * 12 + u;
            const int j = __shfl_sync(0xffffffffu, jv, m);
            wv[u] = __shfl_sync(0xffffffffu, wm, m);
            ga[u] = ((const float2*)(atom + (size_t)j * AA))[lane];
            nb[u] = nrow[m * BB + lane];
        }
        #pragma unroll
        for (int u = 0; u < 12; u++) {
            a0   = fmaf(wv[u], ga[u].x, a0);
            a1   = fmaf(wv[u], ga[u].y, a1);
            bacc = fmaf(wv[u], nb[u], bacc);
        }
    }

    const float2 aself = ((const float2*)(atom + (size_t)n * AA))[lane];
    float* t = g_t + (size_t)n * KK;
    ((float2*)t)[lane]        = make_float2(aself.x * s, aself.y * s);
    ((float2*)(t + 64))[lane] = make_float2(a0, a1);
    t[128 + lane] = bacc;
}

// ---------------- kernel 2: GEMM, 32-row tiles, 2 CTAs/SM, reg-pipelined A (proven) ----------------
#define SMEM_G ((2 * TILE_M * TPAD + 2 * 128 * TPAD) * 2 + (OO + 2 * OO) * 4)

__global__ void __launch_bounds__(NTHR, 2)
k_gemmP(const float* __restrict__ W, const float* __restrict__ bias) {
    extern __shared__ char smem_raw[];
    __nv_bfloat16* sAh = (__nv_bfloat16*)smem_raw;
    __nv_bfloat16* sAl = sAh + TILE_M * TPAD;
    __nv_bfloat16* sWh = sAl + TILE_M * TPAD;
    __nv_bfloat16* sWl = sWh + 128 * TPAD;
    float* sb    = (float*)(sWl + 128 * TPAD);
    float* sstat = sb + OO;

    const int tid  = threadIdx.x;
    const int lane = tid & 31;
    const int warp = tid >> 5;

    for (int i = tid; i < OO * KK / 2; i += NTHR) {
        const int row = i / (KK / 2);
        const int c2  = i % (KK / 2);
        const float2 v = ((const float2*)W)[i];
        float lx, ly;
        __nv_bfloat162 h2 = split_hi2(v.x, v.y, lx, ly);
        ((__nv_bfloat162*)(sWh + row * TPAD))[c2] = h2;
        ((__nv_bfloat162*)(sWl + row * TPAD))[c2] =
            __halves2bfloat162(__float2bfloat16(lx), __float2bfloat16(ly));
    }
    if (tid < OO) sb[tid] = bias[tid];
    if (tid < 2 * OO) sstat[tid] = 0.0f;

    const int rowhalf = warp & 1;
    const int colq    = warp >> 1;
    const int cbase   = (lane & 3) * 2;
    const int rrow    = lane >> 2;

    float4 vreg[4];

    int tile = blockIdx.x;
    if (tile < NT2) {
        const int n0p = tile * TILE_M;
        #pragma unroll
        for (int q = 0; q < 4; q++) {
            const int i = tid + q * NTHR;
            float4 v = make_float4(0.f, 0.f, 0.f, 0.f);
            if (i < TILE_M * 40) {
                const int n = n0p + i / 40;
                if (n < NN)
                    v = *(const float4*)(g_t + (size_t)n * KK + (i % 40) * 4);
            }
            vreg[q] = v;
        }
    }

    for (; tile < NT2; tile += gridDim.x) {
        const int n0 = tile * TILE_M;
        __syncthreads();

        #pragma unroll
        for (int q = 0; q < 4; q++) {
            const int i = tid + q * NTHR;
            if (i < TILE_M * 40) {
                const int r  = i / 40;
                const int c4 = (i % 40) * 4;
                const float4 v = vreg[q];
                float l0, l1, l2, l3;
                __nv_bfloat162 h01 = split_hi2(v.x, v.y, l0, l1);
                __nv_bfloat162 h23 = split_hi2(v.z, v.w, l2, l3);
                __nv_bfloat162* dh = (__nv_bfloat162*)(sAh + r * TPAD + c4);
                __nv_bfloat162* dl = (__nv_bfloat162*)(sAl + r * TPAD + c4);
                dh[0] = h01;
                dh[1] = h23;
                dl[0] = __halves2bfloat162(__float2bfloat16(l0), __float2bfloat16(l1));
                dl[1] = __halves2bfloat162(__float2bfloat16(l2), __float2bfloat16(l3));
            }
        }
        __syncthreads();

        const int nt = tile + gridDim.x;
        if (nt < NT2) {
            const int n0n = nt * TILE_M;
            #pragma unroll
            for (int q = 0; q < 4; q++) {
                const int i = tid + q * NTHR;
                float4 v = make_float4(0.f, 0.f, 0.f, 0.f);
                if (i < TILE_M * 40) {
                    const int n = n0n + i / 40;
                    if (n < NN)
                        v = *(const float4*)(g_t + (size_t)n * KK + (i % 40) * 4);
                }
                vreg[q] = v;
            }
        }

        if (warp < 8) {
            float acc[4][4];
            #pragma unroll
            for (int i = 0; i < 4; i++)
                acc[i][0] = acc[i][1] = acc[i][2] = acc[i][3] = 0.f;

            #pragma unroll 1
            for (int kc = 0; kc < 10; kc++) {
                const int k0 = kc * 16;
                const int arow = rowhalf * 16 + (lane & 15);
                const int acol = k0 + (lane >> 4) * 8;
                uint32_t ah[4], al[4];
                ldsm_x4(ah, smem_u32(sAh + arow * TPAD + acol));
                ldsm_x4(al, smem_u32(sAl + arow * TPAD + acol));

                const int brow_base = ((lane >> 4) & 1) * 8 + (lane & 7);
                const int bcol = k0 + ((lane >> 3) & 1) * 8;
                #pragma unroll
                for (int np = 0; np < 2; np++) {
                    const int brow = colq * 32 + np * 16 + brow_base;
                    uint32_t bh[4], bl[4];
                    ldsm_x4(bh, smem_u32(sWh + brow * TPAD + bcol));
                    ldsm_x4(bl, smem_u32(sWl + brow * TPAD + bcol));
                    mma16816(acc[2 * np],     ah, bh[0], bh[1]);
                    mma16816(acc[2 * np],     al, bh[0], bh[1]);
                    mma16816(acc[2 * np],     ah, bl[0], bl[1]);
                    mma16816(acc[2 * np + 1], ah, bh[2], bh[3]);
                    mma16816(acc[2 * np + 1], al, bh[2], bh[3]);
                    mma16816(acc[2 * np + 1], ah, bl[2], bl[3]);
                }
            }

            const int r0 = n0 + rowhalf * 16 + rrow;
            const bool v0 = (r0 < NN);
            const bool v1 = (r0 + 8 < NN);
            #pragma unroll
            for (int n8 = 0; n8 < 4; n8++) {
                const int col = colq * 32 + n8 * 8 + cbase;
                const float b0 = sb[col], b1 = sb[col + 1];
                float ps0 = 0.f, ps1 = 0.f, pq0 = 0.f, pq1 = 0.f;
                if (v0) {
                    const float y0 = acc[n8][0] + b0;
                    const float y1 = acc[n8][1] + b1;
                    *(float2*)(g_y + (size_t)r0 * OO + col) = make_float2(y0, y1);
                    ps0 += y0; pq0 += y0 * y0;
                    ps1 += y1; pq1 += y1 * y1;
                }
                if (v1) {
                    const float y2 = acc[n8][2] + b0;
                    const float y3 = acc[n8][3] + b1;
                    *(float2*)(g_y + (size_t)(r0 + 8) * OO + col) = make_float2(y2, y3);
                    ps0 += y2; pq0 += y2 * y2;
                    ps1 += y3; pq1 += y3 * y3;
                }
                #pragma unroll
                for (int mk = 4; mk <= 16; mk <<= 1) {
                    ps0 += __shfl_xor_sync(0xffffffffu, ps0, mk);
                    pq0 += __shfl_xor_sync(0xffffffffu, pq0, mk);
                    ps1 += __shfl_xor_sync(0xffffffffu, ps1, mk);
                    pq1 += __shfl_xor_sync(0xffffffffu, pq1, mk);
                }
                if (lane < 4) {
                    const int cl = colq * 32 + n8 * 8 + lane * 2;
                    atomicAdd(&sstat[cl], ps0);
                    atomicAdd(&sstat[OO + cl], pq0);
                    atomicAdd(&sstat[cl + 1], ps1);
                    atomicAdd(&sstat[OO + cl + 1], pq1);
                }
            }
        }
    }

    __syncthreads();
    if (tid < 2 * OO) atomicAdd(&g_stats1[tid], sstat[tid]);
}

// ---------------- kernel 3: gate (BN1 per-block) + BN2 stats, MLP-batched ----------------
__global__ void __launch_bounds__(256)
k_gate(const float* __restrict__ gamma1, const float* __restrict__ beta1) {
    __shared__ float sbn[2 * OO];
    __shared__ float sstat[2 * AA];
    const int tid = threadIdx.x;
    if (tid < OO) {
        const float mean = g_stats1[tid] * (1.0f / NN);
        const float var  = g_stats1[OO + tid] * (1.0f / NN) - mean * mean;
        const float sc = gamma1[tid] * rsqrtf(var + EPSV);
        sbn[tid] = sc;
        sbn[OO + tid] = beta1[tid] - mean * sc;
    }
    if (tid < 2 * AA) sstat[tid] = 0.0f;
    __syncthreads();

    const int stride = EBLK * 256;           // multiple of 16
    const int i0 = blockIdx.x * 256 + tid;
    const int fo = 4 * (i0 & 15);            // invariant feature-quad

    const float4 scf = *(const float4*)(sbn + fo);
    const float4 scc = *(const float4*)(sbn + AA + fo);
    const float4 shf = *(const float4*)(sbn + OO + fo);
    const float4 shc = *(const float4*)(sbn + OO + AA + fo);

    float psum[4] = {0.f, 0.f, 0.f, 0.f};
    float psq[4]  = {0.f, 0.f, 0.f, 0.f};

    int i = i0;
    // batched main loop: 8 independent float4 loads in flight per thread
    for (; i + 3 * stride < TOT4; i += 4 * stride) {
        float4 yf[4], yc[4];
        #pragma unroll
        for (int u = 0; u < 4; u++) {
            const int n = (i + u * stride) >> 4;
            yf[u] = *(const float4*)(g_y + (size_t)n * OO + fo);
            yc[u] = *(const float4*)(g_y + (size_t)n * OO + AA + fo);
        }
        #pragma unroll
        for (int u = 0; u < 4; u++) {
            float4 co;
            co.x = __fdividef(1.0f, 1.0f + __expf(-fmaf(yf[u].x, scf.x, shf.x)))
                   * softplus_fast(fmaf(yc[u].x, scc.x, shc.x));
            co.y = __fdividef(1.0f, 1.0f + __expf(-fmaf(yf[u].y, scf.y, shf.y)))
                   * softplus_fast(fmaf(yc[u].y, scc.y, shc.y));
            co.z = __fdividef(1.0f, 1.0f + __expf(-fmaf(yf[u].z, scf.z, shf.z)))
                   * softplus_fast(fmaf(yc[u].z, scc.z, shc.z));
            co.w = __fdividef(1.0f, 1.0f + __expf(-fmaf(yf[u].w, scf.w, shf.w)))
                   * softplus_fast(fmaf(yc[u].w, scc.w, shc.w));
            ((float4*)g_core)[i + u * stride] = co;
            psum[0] += co.x; psq[0] += co.x * co.x;
            psum[1] += co.y; psq[1] += co.y * co.y;
            psum[2] += co.z; psq[2] += co.z * co.z;
            psum[3] += co.w; psq[3] += co.w * co.w;
        }
    }
    // scalar tail
    for (; i < TOT4; i += stride) {
        const int n = i >> 4;
        const float4 yf = *(const float4*)(g_y + (size_t)n * OO + fo);
        const float4 yc = *(const float4*)(g_y + (size_t)n * OO + AA + fo);
        float4 co;
        co.x = __fdividef(1.0f, 1.0f + __expf(-fmaf(yf.x, scf.x, shf.x)))
               * softplus_fast(fmaf(yc.x, scc.x, shc.x));
        co.y = __fdividef(1.0f, 1.0f + __expf(-fmaf(yf.y, scf.y, shf.y)))
               * softplus_fast(fmaf(yc.y, scc.y, shc.y));
        co.z = __fdividef(1.0f, 1.0f + __expf(-fmaf(yf.z, scf.z, shf.z)))
               * softplus_fast(fmaf(yc.z, scc.z, shc.z));
        co.w = __fdividef(1.0f, 1.0f + __expf(-fmaf(yf.w, scf.w, shf.w)))
               * softplus_fast(fmaf(yc.w, scc.w, shc.w));
        ((float4*)g_core)[i] = co;
        psum[0] += co.x; psq[0] += co.x * co.x;
        psum[1] += co.y; psq[1] += co.y * co.y;
        psum[2] += co.z; psq[2] += co.z * co.z;
        psum[3] += co.w; psq[3] += co.w * co.w;
    }

    #pragma unroll
    for (int c = 0; c < 4; c++) {
        atomicAdd(&sstat[fo + c], psum[c]);
        atomicAdd(&sstat[AA + fo + c], psq[c]);
    }
    __syncthreads();
    if (tid < 2 * AA) atomicAdd(&g_stats2[tid], sstat[tid]);
}

// ---------------- kernel 4: out = softplus(BN2(core)), MLP-batched ----------------
__global__ void __launch_bounds__(256)
k_out(const float* __restrict__ gamma2, const float* __restrict__ beta2,
      float* __restrict__ out) {
    __shared__ float sbn[2 * AA];
    const int tid = threadIdx.x;
    if (tid < AA) {
        const float mean = g_stats2[tid] * (1.0f / NN);
        const float var  = g_stats2[AA + tid] * (1.0f / NN) - mean * mean;
        const float sc = gamma2[tid] * rsqrtf(var + EPSV);
        sbn[tid] = sc;
        sbn[AA + tid] = beta2[tid] - mean * sc;
    }
    __syncthreads();

    const int stride = EBLK * 256;
    const int i0 = blockIdx.x * 256 + tid;
    const int fo = 4 * (i0 & 15);

    const float4 sc4 = *(const float4*)(sbn + fo);
    const float4 sh4 = *(const float4*)(sbn + AA + fo);

    int i = i0;
    for (; i + 3 * stride < TOT4; i += 4 * stride) {
        float4 cv[4];
        #pragma unroll
        for (int u = 0; u < 4; u++)
            cv[u] = ((const float4*)g_core)[i + u * stride];
        #pragma unroll
        for (int u = 0; u < 4; u++) {
            float4 o;
            o.x = softplus_fast(fmaf(cv[u].x, sc4.x, sh4.x));
            o.y = softplus_fast(fmaf(cv[u].y, sc4.y, sh4.y));
            o.z = softplus_fast(fmaf(cv[u].z, sc4.z, sh4.z));
            o.w = softplus_fast(fmaf(cv[u].w, sc4.w, sh4.w));
            ((float4*)out)[i + u * stride] = o;
        }
    }
    for (; i < TOT4; i += stride) {
        const float4 c = ((const float4*)g_core)[i];
        float4 o;
        o.x = softplus_fast(fmaf(c.x, sc4.x, sh4.x));
        o.y = softplus_fast(fmaf(c.y, sc4.y, sh4.y));
        o.z = softplus_fast(fmaf(c.z, sc4.z, sh4.z));
        o.w = softplus_fast(fmaf(c.w, sc4.w, sh4.w));
        ((float4*)out)[i] = o;
    }
}

// ---------------- launcher ----------------
extern "C" void kernel_launch(void* const* d_in, const int* in_sizes, int n_in,
                              void* d_out, int out_size) {
    const float* atom   = (const float*)d_in[0];
    const float* nbrfea = (const float*)d_in[1];
    const int*   nbridx = (const int*)d_in[2];
    const float* bwi    = (const float*)d_in[3];
    const float* bwj    = (const float*)d_in[4];
    const float* W      = (const float*)d_in[5];
    const float* bias   = (const float*)d_in[6];
    const float* gamma1 = (const float*)d_in[7];
    const float* beta1  = (const float*)d_in[8];
    const float* gamma2 = (const float*)d_in[9];
    const float* beta2  = (const float*)d_in[10];
    float*       out    = (float*)d_out;

    cudaFuncSetAttribute(k_gemmP, cudaFuncAttributeMaxDynamicSharedMemorySize, SMEM_G);

    k_feat<<<NN / 4, 128>>>(atom, nbrfea, nbridx, bwi, bwj);
    k_gemmP<<<NCTA2, NTHR, SMEM_G>>>(W, bias);
    k_gate<<<EBLK, 256>>>(gamma1, beta1);
    k_out<<<EBLK, 256>>>(gamma2, beta2, out);
}

// round 17
// speedup vs baseline: 1.0037x; 1.0037x over previous
#include <cuda_runtime.h>
#include <cuda_bf16.h>
#include <cstdint>

#define NN 50000
#define MM 24
#define AA 64
#define BB 32
#define KK 160   // 2A + B
#define OO 128   // 2A
#define EPSV 1e-5f
#define TPAD 168          // padded row stride (elements) for smem bf16 tiles
#define TILE_M 32
#define NT2 1563          // ceil(50000/32)
#define NCTA2 296         // 2 CTAs per SM
#define NTHR 384
#define EBLK 592          // elementwise kernels: 4 blocks/SM
#define TOT4 (NN * (AA / 4))      // 800000 float4 elements

// ---------------- scratch (static __device__, zero-init at load) ----------------
__device__ float g_t[(size_t)NN * KK];      // 32 MB
__device__ float g_y[(size_t)NN * OO];      // 25.6 MB
__device__ float g_core[(size_t)NN * AA];   // 12.8 MB
__device__ float g_stats1[2 * OO];          // re-zeroed by k_feat block 0 (ALL 256 entries)
__device__ float g_stats2[2 * AA];          // re-zeroed by k_feat block 0

// ---------------- helpers ----------------
__device__ __forceinline__ float softplus_fast(float x) {
    return fmaxf(x, 0.0f) + __logf(1.0f + __expf(-fabsf(x)));
}
__device__ __forceinline__ uint32_t smem_u32(const void* p) {
    return (uint32_t)__cvta_generic_to_shared(p);
}
__device__ __forceinline__ void ldsm_x4(uint32_t* r, uint32_t addr) {
    asm volatile("ldmatrix.sync.aligned.m8n8.x4.shared.b16 {%0,%1,%2,%3}, [%4];"
                 : "=r"(r[0]), "=r"(r[1]), "=r"(r[2]), "=r"(r[3]) : "r"(addr));
}
__device__ __forceinline__ void mma16816(float* d, const uint32_t* a,
                                         const uint32_t b0, const uint32_t b1) {
    asm volatile(
        "mma.sync.aligned.m16n8k16.row.col.f32.bf16.bf16.f32 "
        "{%0,%1,%2,%3}, {%4,%5,%6,%7}, {%8,%9}, {%0,%1,%2,%3};"
        : "+f"(d[0]), "+f"(d[1]), "+f"(d[2]), "+f"(d[3])
        : "r"(a[0]), "r"(a[1]), "r"(a[2]), "r"(a[3]), "r"(b0), "r"(b1));
}
__device__ __forceinline__ __nv_bfloat162 split_hi2(float x, float y,
                                                    float& rx, float& ry) {
    __nv_bfloat16 hx = __float2bfloat16(x);
    __nv_bfloat16 hy = __float2bfloat16(y);
    rx = x - __bfloat162float(hx);
    ry = y - __bfloat162float(hy);
    return __halves2bfloat162(hx, hy);
}

// ---------------- kernel 1: gather/reduce, occupancy-tuned ----------------
// batch of 8 (3 chunks): ~32 array regs; __launch_bounds__(128,8) -> 32 warps/SM
__global__ void __launch_bounds__(128, 8)
k_feat(const float* __restrict__ atom,
       const float* __restrict__ nbrfea,
       const int* __restrict__ nbridx,
       const float* __restrict__ bwi,
       const float* __restrict__ bwj) {
    if (blockIdx.x == 0) {
        for (int t = threadIdx.x; t < 2 * OO; t += 128) g_stats1[t] = 0.0f;
        if (threadIdx.x < 2 * AA) g_stats2[threadIdx.x] = 0.0f;
    }

    const int lane = threadIdx.x & 31;
    const int warp = threadIdx.x >> 5;
    const int n = blockIdx.x * 4 + warp;   // 12500*4 = 50000 exact

    float wm = 0.0f;
    int jv = 0;
    if (lane < MM) {
        wm = bwi[(size_t)n * MM + lane] * bwj[(size_t)n * MM + lane];
        jv = nbridx[(size_t)n * MM + lane];
    }
    float s = wm;
    #pragma unroll
    for (int o = 16; o; o >>= 1) s += __shfl_xor_sync(0xffffffffu, s, o);

    float a0 = 0.f, a1 = 0.f, bacc = 0.f;
    const float* nrow = nbrfea + (size_t)n * MM * BB;

    #pragma unroll
    for (int c = 0; c < 3; c++) {
        float2 ga[8];
        float  nb[8];
        float  wv[8];
        #pragma unroll
        for (int u = 0; u < 8; u++) {
            const int m = c * 8 + u;
            const int j = __shfl_sync(0xffffffffu, jv, m);
            wv[u] = __shfl_sync(0xffffffffu, wm, m);
            ga[u] = ((const float2*)(atom + (size_t)j * AA))[lane];
            nb[u] = nrow[m * BB + lane];
        }
        #pragma unroll
        for (int u = 0; u < 8; u++) {
            a0   = fmaf(wv[u], ga[u].x, a0);
            a1   = fmaf(wv[u], ga[u].y, a1);
            bacc = fmaf(wv[u], nb[u], bacc);
        }
    }

    const float2 aself = ((const float2*)(atom + (size_t)n * AA))[lane];
    float* t = g_t + (size_t)n * KK;
    ((float2*)t)[lane]        = make_float2(aself.x * s, aself.y * s);
    ((float2*)(t + 64))[lane] = make_float2(a0, a1);
    t[128 + lane] = bacc;
}

// ---------------- kernel 2: GEMM, 32-row tiles, 2 CTAs/SM, reg-pipelined A (proven) ----------------
#define SMEM_G ((2 * TILE_M * TPAD + 2 * 128 * TPAD) * 2 + (OO + 2 * OO) * 4)

__global__ void __launch_bounds__(NTHR, 2)
k_gemmP(const float* __restrict__ W, const float* __restrict__ bias) {
    extern __shared__ char smem_raw[];
    __nv_bfloat16* sAh = (__nv_bfloat16*)smem_raw;
    __nv_bfloat16* sAl = sAh + TILE_M * TPAD;
    __nv_bfloat16* sWh = sAl + TILE_M * TPAD;
    __nv_bfloat16* sWl = sWh + 128 * TPAD;
    float* sb    = (float*)(sWl + 128 * TPAD);
    float* sstat = sb + OO;

    const int tid  = threadIdx.x;
    const int lane = tid & 31;
    const int warp = tid >> 5;

    for (int i = tid; i < OO * KK / 2; i += NTHR) {
        const int row = i / (KK / 2);
        const int c2  = i % (KK / 2);
        const float2 v = ((const float2*)W)[i];
        float lx, ly;
        __nv_bfloat162 h2 = split_hi2(v.x, v.y, lx, ly);
        ((__nv_bfloat162*)(sWh + row * TPAD))[c2] = h2;
        ((__nv_bfloat162*)(sWl + row * TPAD))[c2] =
            __halves2bfloat162(__float2bfloat16(lx), __float2bfloat16(ly));
    }
    if (tid < OO) sb[tid] = bias[tid];
    if (tid < 2 * OO) sstat[tid] = 0.0f;

    const int rowhalf = warp & 1;
    const int colq    = warp >> 1;
    const int cbase   = (lane & 3) * 2;
    const int rrow    = lane >> 2;

    float4 vreg[4];

    int tile = blockIdx.x;
    if (tile < NT2) {
        const int n0p = tile * TILE_M;
        #pragma unroll
        for (int q = 0; q < 4; q++) {
            const int i = tid + q * NTHR;
            float4 v = make_float4(0.f, 0.f, 0.f, 0.f);
            if (i < TILE_M * 40) {
                const int n = n0p + i / 40;
                if (n < NN)
                    v = *(const float4*)(g_t + (size_t)n * KK + (i % 40) * 4);
            }
            vreg[q] = v;
        }
    }

    for (; tile < NT2; tile += gridDim.x) {
        const int n0 = tile * TILE_M;
        __syncthreads();

        #pragma unroll
        for (int q = 0; q < 4; q++) {
            const int i = tid + q * NTHR;
            if (i < TILE_M * 40) {
                const int r  = i / 40;
                const int c4 = (i % 40) * 4;
                const float4 v = vreg[q];
                float l0, l1, l2, l3;
                __nv_bfloat162 h01 = split_hi2(v.x, v.y, l0, l1);
                __nv_bfloat162 h23 = split_hi2(v.z, v.w, l2, l3);
                __nv_bfloat162* dh = (__nv_bfloat162*)(sAh + r * TPAD + c4);
                __nv_bfloat162* dl = (__nv_bfloat162*)(sAl + r * TPAD + c4);
                dh[0] = h01;
                dh[1] = h23;
                dl[0] = __halves2bfloat162(__float2bfloat16(l0), __float2bfloat16(l1));
                dl[1] = __halves2bfloat162(__float2bfloat16(l2), __float2bfloat16(l3));
            }
        }
        __syncthreads();

        const int nt = tile + gridDim.x;
        if (nt < NT2) {
            const int n0n = nt * TILE_M;
            #pragma unroll
            for (int q = 0; q < 4; q++) {
                const int i = tid + q * NTHR;
                float4 v = make_float4(0.f, 0.f, 0.f, 0.f);
                if (i < TILE_M * 40) {
                    const int n = n0n + i / 40;
                    if (n < NN)
                        v = *(const float4*)(g_t + (size_t)n * KK + (i % 40) * 4);
                }
                vreg[q] = v;
            }
        }

        if (warp < 8) {
            float acc[4][4];
            #pragma unroll
            for (int i = 0; i < 4; i++)
                acc[i][0] = acc[i][1] = acc[i][2] = acc[i][3] = 0.f;

            #pragma unroll 1
            for (int kc = 0; kc < 10; kc++) {
                const int k0 = kc * 16;
                const int arow = rowhalf * 16 + (lane & 15);
                const int acol = k0 + (lane >> 4) * 8;
                uint32_t ah[4], al[4];
                ldsm_x4(ah, smem_u32(sAh + arow * TPAD + acol));
                ldsm_x4(al, smem_u32(sAl + arow * TPAD + acol));

                const int brow_base = ((lane >> 4) & 1) * 8 + (lane & 7);
                const int bcol = k0 + ((lane >> 3) & 1) * 8;
                #pragma unroll
                for (int np = 0; np < 2; np++) {
                    const int brow = colq * 32 + np * 16 + brow_base;
                    uint32_t bh[4], bl[4];
                    ldsm_x4(bh, smem_u32(sWh + brow * TPAD + bcol));
                    ldsm_x4(bl, smem_u32(sWl + brow * TPAD + bcol));
                    mma16816(acc[2 * np],     ah, bh[0], bh[1]);
                    mma16816(acc[2 * np],     al, bh[0], bh[1]);
                    mma16816(acc[2 * np],     ah, bl[0], bl[1]);
                    mma16816(acc[2 * np + 1], ah, bh[2], bh[3]);
                    mma16816(acc[2 * np + 1], al, bh[2], bh[3]);
                    mma16816(acc[2 * np + 1], ah, bl[2], bl[3]);
                }
            }

            const int r0 = n0 + rowhalf * 16 + rrow;
            const bool v0 = (r0 < NN);
            const bool v1 = (r0 + 8 < NN);
            #pragma unroll
            for (int n8 = 0; n8 < 4; n8++) {
                const int col = colq * 32 + n8 * 8 + cbase;
                const float b0 = sb[col], b1 = sb[col + 1];
                float ps0 = 0.f, ps1 = 0.f, pq0 = 0.f, pq1 = 0.f;
                if (v0) {
                    const float y0 = acc[n8][0] + b0;
                    const float y1 = acc[n8][1] + b1;
                    *(float2*)(g_y + (size_t)r0 * OO + col) = make_float2(y0, y1);
                    ps0 += y0; pq0 += y0 * y0;
                    ps1 += y1; pq1 += y1 * y1;
                }
                if (v1) {
                    const float y2 = acc[n8][2] + b0;
                    const float y3 = acc[n8][3] + b1;
                    *(float2*)(g_y + (size_t)(r0 + 8) * OO + col) = make_float2(y2, y3);
                    ps0 += y2; pq0 += y2 * y2;
                    ps1 += y3; pq1 += y3 * y3;
                }
                #pragma unroll
                for (int mk = 4; mk <= 16; mk <<= 1) {
                    ps0 += __shfl_xor_sync(0xffffffffu, ps0, mk);
                    pq0 += __shfl_xor_sync(0xffffffffu, pq0, mk);
                    ps1 += __shfl_xor_sync(0xffffffffu, ps1, mk);
                    pq1 += __shfl_xor_sync(0xffffffffu, pq1, mk);
                }
                if (lane < 4) {
                    const int cl = colq * 32 + n8 * 8 + lane * 2;
                    atomicAdd(&sstat[cl], ps0);
                    atomicAdd(&sstat[OO + cl], pq0);
                    atomicAdd(&sstat[cl + 1], ps1);
                    atomicAdd(&sstat[OO + cl + 1], pq1);
                }
            }
        }
    }

    __syncthreads();
    if (tid < 2 * OO) atomicAdd(&g_stats1[tid], sstat[tid]);
}

// ---------------- kernel 3: gate (BN1 per-block) + BN2 stats, MLP-batched ----------------
__global__ void __launch_bounds__(256)
k_gate(const float* __restrict__ gamma1, const float* __restrict__ beta1) {
    __shared__ float sbn[2 * OO];
    __shared__ float sstat[2 * AA];
    const int tid = threadIdx.x;
    if (tid < OO) {
        const float mean = g_stats1[tid] * (1.0f / NN);
        const float var  = g_stats1[OO + tid] * (1.0f / NN) - mean * mean;
        const float sc = gamma1[tid] * rsqrtf(var + EPSV);
        sbn[tid] = sc;
        sbn[OO + tid] = beta1[tid] - mean * sc;
    }
    if (tid < 2 * AA) sstat[tid] = 0.0f;
    __syncthreads();

    const int stride = EBLK * 256;
    const int i0 = blockIdx.x * 256 + tid;
    const int fo = 4 * (i0 & 15);

    const float4 scf = *(const float4*)(sbn + fo);
    const float4 scc = *(const float4*)(sbn + AA + fo);
    const float4 shf = *(const float4*)(sbn + OO + fo);
    const float4 shc = *(const float4*)(sbn + OO + AA + fo);

    float psum[4] = {0.f, 0.f, 0.f, 0.f};
    float psq[4]  = {0.f, 0.f, 0.f, 0.f};

    int i = i0;
    for (; i + 3 * stride < TOT4; i += 4 * stride) {
        float4 yf[4], yc[4];
        #pragma unroll
        for (int u = 0; u < 4; u++) {
            const int n = (i + u * stride) >> 4;
            yf[u] = *(const float4*)(g_y + (size_t)n * OO + fo);
            yc[u] = *(const float4*)(g_y + (size_t)n * OO + AA + fo);
        }
        #pragma unroll
        for (int u = 0; u < 4; u++) {
            float4 co;
            co.x = __fdividef(1.0f, 1.0f + __expf(-fmaf(yf[u].x, scf.x, shf.x)))
                   * softplus_fast(fmaf(yc[u].x, scc.x, shc.x));
            co.y = __fdividef(1.0f, 1.0f + __expf(-fmaf(yf[u].y, scf.y, shf.y)))
                   * softplus_fast(fmaf(yc[u].y, scc.y, shc.y));
            co.z = __fdividef(1.0f, 1.0f + __expf(-fmaf(yf[u].z, scf.z, shf.z)))
                   * softplus_fast(fmaf(yc[u].z, scc.z, shc.z));
            co.w = __fdividef(1.0f, 1.0f + __expf(-fmaf(yf[u].w, scf.w, shf.w)))
                   * softplus_fast(fmaf(yc[u].w, scc.w, shc.w));
            ((float4*)g_core)[i + u * stride] = co;
            psum[0] += co.x; psq[0] += co.x * co.x;
            psum[1] += co.y; psq[1] += co.y * co.y;
            psum[2] += co.z; psq[2] += co.z * co.z;
            psum[3] += co.w; psq[3] += co.w * co.w;
        }
    }
    for (; i < TOT4; i += stride) {
        const int n = i >> 4;
        const float4 yf = *(const float4*)(g_y + (size_t)n * OO + fo);
        const float4 yc = *(const float4*)(g_y + (size_t)n * OO + AA + fo);
        float4 co;
        co.x = __fdividef(1.0f, 1.0f + __expf(-fmaf(yf.x, scf.x, shf.x)))
               * softplus_fast(fmaf(yc.x, scc.x, shc.x));
        co.y = __fdividef(1.0f, 1.0f + __expf(-fmaf(yf.y, scf.y, shf.y)))
               * softplus_fast(fmaf(yc.y, scc.y, shc.y));
        co.z = __fdividef(1.0f, 1.0f + __expf(-fmaf(yf.z, scf.z, shf.z)))
               * softplus_fast(fmaf(yc.z, scc.z, shc.z));
        co.w = __fdividef(1.0f, 1.0f + __expf(-fmaf(yf.w, scf.w, shf.w)))
               * softplus_fast(fmaf(yc.w, scc.w, shc.w));
        ((float4*)g_core)[i] = co;
        psum[0] += co.x; psq[0] += co.x * co.x;
        psum[1] += co.y; psq[1] += co.y * co.y;
        psum[2] += co.z; psq[2] += co.z * co.z;
        psum[3] += co.w; psq[3] += co.w * co.w;
    }

    #pragma unroll
    for (int c = 0; c < 4; c++) {
        atomicAdd(&sstat[fo + c], psum[c]);
        atomicAdd(&sstat[AA + fo + c], psq[c]);
    }
    __syncthreads();
    if (tid < 2 * AA) atomicAdd(&g_stats2[tid], sstat[tid]);
}

// ---------------- kernel 4: out = softplus(BN2(core)), MLP-batched ----------------
__global__ void __launch_bounds__(256)
k_out(const float* __restrict__ gamma2, const float* __restrict__ beta2,
      float* __restrict__ out) {
    __shared__ float sbn[2 * AA];
    const int tid = threadIdx.x;
    if (tid < AA) {
        const float mean = g_stats2[tid] * (1.0f / NN);
        const float var  = g_stats2[AA + tid] * (1.0f / NN) - mean * mean;
        const float sc = gamma2[tid] * rsqrtf(var + EPSV);
        sbn[tid] = sc;
        sbn[AA + tid] = beta2[tid] - mean * sc;
    }
    __syncthreads();

    const int stride = EBLK * 256;
    const int i0 = blockIdx.x * 256 + tid;
    const int fo = 4 * (i0 & 15);

    const float4 sc4 = *(const float4*)(sbn + fo);
    const float4 sh4 = *(const float4*)(sbn + AA + fo);

    int i = i0;
    for (; i + 3 * stride < TOT4; i += 4 * stride) {
        float4 cv[4];
        #pragma unroll
        for (int u = 0; u < 4; u++)
            cv[u] = ((const float4*)g_core)[i + u * stride];
        #pragma unroll
        for (int u = 0; u < 4; u++) {
            float4 o;
            o.x = softplus_fast(fmaf(cv[u].x, sc4.x, sh4.x));
            o.y = softplus_fast(fmaf(cv[u].y, sc4.y, sh4.y));
            o.z = softplus_fast(fmaf(cv[u].z, sc4.z, sh4.z));
            o.w = softplus_fast(fmaf(cv[u].w, sc4.w, sh4.w));
            ((float4*)out)[i + u * stride] = o;
        }
    }
    for (; i < TOT4; i += stride) {
        const float4 c = ((const float4*)g_core)[i];
        float4 o;
        o.x = softplus_fast(fmaf(c.x, sc4.x, sh4.x));
        o.y = softplus_fast(fmaf(c.y, sc4.y, sh4.y));
        o.z = softplus_fast(fmaf(c.z, sc4.z, sh4.z));
        o.w = softplus_fast(fmaf(c.w, sc4.w, sh4.w));
        ((float4*)out)[i] = o;
    }
}

// ---------------- launcher ----------------
extern "C" void kernel_launch(void* const* d_in, const int* in_sizes, int n_in,
                              void* d_out, int out_size) {
    const float* atom   = (const float*)d_in[0];
    const float* nbrfea = (const float*)d_in[1];
    const int*   nbridx = (const int*)d_in[2];
    const float* bwi    = (const float*)d_in[3];
    const float* bwj    = (const float*)d_in[4];
    const float* W      = (const float*)d_in[5];
    const float* bias   = (const float*)d_in[6];
    const float* gamma1 = (const float*)d_in[7];
    const float* beta1  = (const float*)d_in[8];
    const float* gamma2 = (const float*)d_in[9];
    const float* beta2  = (const float*)d_in[10];
    float*       out    = (float*)d_out;

    cudaFuncSetAttribute(k_gemmP, cudaFuncAttributeMaxDynamicSharedMemorySize, SMEM_G);

    k_feat<<<NN / 4, 128>>>(atom, nbrfea, nbridx, bwi, bwj);
    k_gemmP<<<NCTA2, NTHR, SMEM_G>>>(W, bias);
    k_gate<<<EBLK, 256>>>(gamma1, beta1);
    k_out<<<EBLK, 256>>>(gamma2, beta2, out);
}